// round 13
// baseline (speedup 1.0000x reference)
#include <cuda_runtime.h>
#include <cuda_bf16.h>
#include <math.h>

// ---------------------------------------------------------------------------
// GAT layer on GB300.
//  msg = x @ W^T  (bf16x2 tensor-core GEMM m16n8k16, W pre-converted to
//                  packed mma fragments held in L1 via LDG)
//  s_src/s_dst fused into GEMM epilogue; edge histogram fused into GEMM tail
//  CSR-by-dst build (fused histogram -> warp-lookback scan -> counting sort)
//  warp-per-node gather (no float atomics)
// ---------------------------------------------------------------------------

#define MAXN   50048
#define MAXE   600064
#define MAXET  (MAXN + MAXE)
#define F      128
#define PAD    132
#define NFRAG  (8 * 16 * 32)   // (ka, j, lane) bf16 B fragments
#define FULLM  0xffffffffu

__device__ float  g_msg[(size_t)MAXN * F];
__device__ float  g_ssrc[MAXN];
__device__ float  g_sdst[MAXN];
__device__ int    g_deg[MAXN];
__device__ int    g_off[MAXN + 1];
__device__ int    g_cur[MAXN];
__device__ float2 g_sw[MAXET];            // packed (src_bits, w)
__device__ unsigned long long g_lbk[64];  // lookback: (state<<32)|value
__device__ int    g_is64;
__device__ uint4  g_bfrag[NFRAG];         // (bh0,bh1,bl0,bl1) per (ka,j,lane)

// ---------------- init: zero hist/lookback + dtype detect + W frag cvt -----
__global__ void k_init(const int* __restrict__ ei32, const float* __restrict__ W,
                       int N) {
    __shared__ int sh[256];
    int i = blockIdx.x * blockDim.x + threadIdx.x;
    if (i < N) g_deg[i] = 0;
    if (i < 64) g_lbk[i] = 0ull;
    // W -> bf16x2 mma fragments (first 4096 threads)
    if (i < NFRAG) {
        int lane = i & 31, j = (i >> 5) & 15, ka = i >> 9;   // ka 0..7
        int g = lane >> 2, tg = lane & 3;
        int row = 8 * j + g, k0 = 16 * ka;
        float f0 = W[row * F + k0 + 2 * tg];
        float f1 = W[row * F + k0 + 2 * tg + 1];
        float f2 = W[row * F + k0 + 2 * tg + 8];
        float f3 = W[row * F + k0 + 2 * tg + 9];
        __nv_bfloat162 h0 = __floats2bfloat162_rn(f0, f1);
        __nv_bfloat162 h1 = __floats2bfloat162_rn(f2, f3);
        __nv_bfloat162 l0 = __floats2bfloat162_rn(f0 - __bfloat162float(h0.x),
                                                  f1 - __bfloat162float(h0.y));
        __nv_bfloat162 l1 = __floats2bfloat162_rn(f2 - __bfloat162float(h1.x),
                                                  f3 - __bfloat162float(h1.y));
        g_bfrag[i] = make_uint4(*(unsigned*)&h0, *(unsigned*)&h1,
                                *(unsigned*)&l0, *(unsigned*)&l1);
    }
    if (blockIdx.x == 0) {
        int any = 0;
        for (int t = threadIdx.x; t < 512; t += 256) any |= ei32[2 * t + 1];
        sh[threadIdx.x] = any;
        __syncthreads();
        for (int s = 128; s > 0; s >>= 1) {
            if (threadIdx.x < s) sh[threadIdx.x] |= sh[threadIdx.x + s];
            __syncthreads();
        }
        if (threadIdx.x == 0) g_is64 = (sh[0] == 0) ? 1 : 0;
    }
}

__device__ __forceinline__ void load_edge(const void* ei, int E, int e,
                                          int& src, int& dst) {
    if (g_is64) {
        const long long* p = (const long long*)ei;
        src = (int)p[e];
        dst = (int)p[E + e];
    } else {
        const int* p = (const int*)ei;
        src = p[e];
        dst = p[E + e];
    }
}

// ---------------- bf16 mma -------------------------------------------------
__device__ __forceinline__ void mma16(float* c,
                                      unsigned a0, unsigned a1, unsigned a2, unsigned a3,
                                      unsigned b0, unsigned b1) {
    asm volatile(
        "mma.sync.aligned.m16n8k16.row.col.f32.bf16.bf16.f32 "
        "{%0,%1,%2,%3}, {%4,%5,%6,%7}, {%8,%9}, {%0,%1,%2,%3};\n"
        : "+f"(c[0]), "+f"(c[1]), "+f"(c[2]), "+f"(c[3])
        : "r"(a0), "r"(a1), "r"(a2), "r"(a3), "r"(b0), "r"(b1));
}

// ---------------- GEMM: msg = x @ W^T (bf16x2) + scores + fused histogram --
// Block: 128 nodes x 128 feats, 256 threads (8 warps), each warp 16 rows.
#define GEMM_SMEM_BYTES ((F * PAD + 2 * F) * (int)sizeof(float))

__global__ void __launch_bounds__(256) k_gemm(const float* __restrict__ x,
                                              const float* __restrict__ a,
                                              const void* __restrict__ ei,
                                              int N, int E, int ET) {
    extern __shared__ float smem[];
    float* As = smem;               // F x PAD
    float* av = smem + F * PAD;     // 2F floats

    const int tid  = threadIdx.x;
    const int warp = tid >> 5;
    const int lane = tid & 31;
    const int g    = lane >> 2;      // 0..7
    const int tg   = lane & 3;       // 0..3
    const int m0   = blockIdx.x * 128;

    if (tid < 256) av[tid] = a[tid];
    for (int idx = tid; idx < F * 32; idx += 256) {
        int r = idx >> 5, c4 = idx & 31;
        int row = m0 + r;
        float4 v = (row < N) ? ((const float4*)x)[(size_t)row * 32 + c4]
                             : make_float4(0.f, 0.f, 0.f, 0.f);
        *(float4*)&As[r * PAD + c4 * 4] = v;
    }
    __syncthreads();

    float acc[16][4];
    #pragma unroll
    for (int j = 0; j < 16; ++j)
        acc[j][0] = acc[j][1] = acc[j][2] = acc[j][3] = 0.f;

    const int mw  = warp * 16;
    const int r0i = (mw + g) * PAD;
    const int r1i = (mw + g + 8) * PAD;
    const uint4* __restrict__ bf = g_bfrag + lane;

    #pragma unroll
    for (int ka = 0; ka < 8; ++ka) {
        const int k0 = ka * 16 + 2 * tg;
        float2 p00 = *(const float2*)&As[r0i + k0];
        float2 p01 = *(const float2*)&As[r0i + k0 + 8];
        float2 p10 = *(const float2*)&As[r1i + k0];
        float2 p11 = *(const float2*)&As[r1i + k0 + 8];

        __nv_bfloat162 h0 = __floats2bfloat162_rn(p00.x, p00.y);
        __nv_bfloat162 h1 = __floats2bfloat162_rn(p10.x, p10.y);
        __nv_bfloat162 h2 = __floats2bfloat162_rn(p01.x, p01.y);
        __nv_bfloat162 h3 = __floats2bfloat162_rn(p11.x, p11.y);
        __nv_bfloat162 l0 = __floats2bfloat162_rn(p00.x - __bfloat162float(h0.x),
                                                  p00.y - __bfloat162float(h0.y));
        __nv_bfloat162 l1 = __floats2bfloat162_rn(p10.x - __bfloat162float(h1.x),
                                                  p10.y - __bfloat162float(h1.y));
        __nv_bfloat162 l2 = __floats2bfloat162_rn(p01.x - __bfloat162float(h2.x),
                                                  p01.y - __bfloat162float(h2.y));
        __nv_bfloat162 l3 = __floats2bfloat162_rn(p11.x - __bfloat162float(h3.x),
                                                  p11.y - __bfloat162float(h3.y));
        unsigned ah0 = *(unsigned*)&h0, ah1 = *(unsigned*)&h1;
        unsigned ah2 = *(unsigned*)&h2, ah3 = *(unsigned*)&h3;
        unsigned al0 = *(unsigned*)&l0, al1 = *(unsigned*)&l1;
        unsigned al2 = *(unsigned*)&l2, al3 = *(unsigned*)&l3;

        #pragma unroll
        for (int j = 0; j < 16; ++j) {
            uint4 b = __ldg(bf + (ka * 16 + j) * 32);
            mma16(acc[j], ah0, ah1, ah2, ah3, b.x, b.y);  // hi*hi
            mma16(acc[j], ah0, ah1, ah2, ah3, b.z, b.w);  // hi*lo
            mma16(acc[j], al0, al1, al2, al3, b.x, b.y);  // lo*hi
        }
    }

    // ---- fused attention scores: s = msg @ a -------------------------------
    float p0 = 0.f, q0 = 0.f, p1 = 0.f, q1 = 0.f;  // rows g, g+8
    #pragma unroll
    for (int j = 0; j < 16; ++j) {
        int c = 8 * j + 2 * tg;
        p0 += acc[j][0] * av[c]       + acc[j][1] * av[c + 1];
        q0 += acc[j][0] * av[F + c]   + acc[j][1] * av[F + c + 1];
        p1 += acc[j][2] * av[c]       + acc[j][3] * av[c + 1];
        q1 += acc[j][2] * av[F + c]   + acc[j][3] * av[F + c + 1];
    }
    #pragma unroll
    for (int off = 1; off < 4; off <<= 1) {
        p0 += __shfl_xor_sync(FULLM, p0, off);
        q0 += __shfl_xor_sync(FULLM, q0, off);
        p1 += __shfl_xor_sync(FULLM, p1, off);
        q1 += __shfl_xor_sync(FULLM, q1, off);
    }
    if (tg == 0) {
        int r0 = m0 + mw + g, r1 = r0 + 8;
        if (r0 < N) { g_ssrc[r0] = p0; g_sdst[r0] = q0; }
        if (r1 < N) { g_ssrc[r1] = p1; g_sdst[r1] = q1; }
    }

    // ---- stage accumulators to (warp-private) SMEM, store coalesced --------
    __syncwarp();
    #pragma unroll
    for (int j = 0; j < 16; ++j) {
        int c = 8 * j + 2 * tg;
        *(float2*)&As[r0i + c] = make_float2(acc[j][0], acc[j][1]);
        *(float2*)&As[r1i + c] = make_float2(acc[j][2], acc[j][3]);
    }
    __syncwarp();
    for (int idx = lane; idx < 512; idx += 32) {
        int r = idx >> 5, c4 = idx & 31;
        int row = m0 + mw + r;
        if (row < N)
            *(float4*)&g_msg[(size_t)row * F + c4 * 4] =
                *(float4*)&As[(mw + r) * PAD + c4 * 4];
    }

    // ---- fused degree histogram chunk (independent of GEMM results) --------
    {
        int per = (ET + gridDim.x - 1) / gridDim.x;
        int e0 = blockIdx.x * per;
        int e1 = min(e0 + per, ET);
        if (g_is64) {
            const long long* __restrict__ pd = (const long long*)ei + E;
            for (int e = e0 + tid; e < e1; e += 256) {
                int dst = (e < E) ? (int)pd[e] : e - E;
                atomicAdd(&g_deg[dst], 1);
            }
        } else {
            const int* __restrict__ pd = (const int*)ei + E;
            for (int e = e0 + tid; e < e1; e += 256) {
                int dst = (e < E) ? pd[e] : e - E;
                atomicAdd(&g_deg[dst], 1);
            }
        }
    }
}

// Single-kernel decoupled-lookback exclusive scan (warp-parallel lookback).
__global__ void k_scan(int n, int total) {
    __shared__ int wsum[32];
    __shared__ int s_prefix;
    const int tid = threadIdx.x, lane = tid & 31, warp = tid >> 5;
    const int b = blockIdx.x;
    const int i = b * 1024 + tid;
    int v = (i < n) ? g_deg[i] : 0;
    int s = v;
    #pragma unroll
    for (int off = 1; off < 32; off <<= 1) {
        int t = __shfl_up_sync(FULLM, s, off);
        if (lane >= off) s += t;
    }
    if (lane == 31) wsum[warp] = s;
    __syncthreads();
    if (warp == 0) {
        int ws = wsum[lane];
        #pragma unroll
        for (int off = 1; off < 32; off <<= 1) {
            int t = __shfl_up_sync(FULLM, ws, off);
            if (lane >= off) ws += t;
        }
        wsum[lane] = ws;
    }
    __syncthreads();
    int agg = wsum[31];

    if (warp == 0) {
        if (b == 0) {
            if (lane == 0) {
                atomicExch(&g_lbk[0], (2ull << 32) | (unsigned)agg);
                s_prefix = 0;
            }
        } else {
            if (lane == 0)
                atomicExch(&g_lbk[b], (1ull << 32) | (unsigned)agg);
            __syncwarp();
            // warp-parallel lookback: lane L inspects predecessor b-1-L
            int prefix = 0;
            int p = b - 1 - lane;
            while (true) {
                unsigned long long val = (p >= 0)
                    ? *(volatile unsigned long long*)&g_lbk[p]
                    : (2ull << 32);
                unsigned st = (unsigned)(val >> 32);
                if (!__all_sync(FULLM, st != 0)) continue;   // retry window
                unsigned m2 = __ballot_sync(FULLM, st == 2);
                if (m2) {
                    int l2 = __ffs(m2) - 1;  // closest inclusive-prefix block
                    int contrib = (lane <= l2) ? (int)(unsigned)val : 0;
                    prefix += __reduce_add_sync(FULLM, contrib);
                    break;
                } else {
                    prefix += __reduce_add_sync(FULLM, (int)(unsigned)val);
                    p -= 32;
                }
            }
            if (lane == 0) {
                atomicExch(&g_lbk[b], (2ull << 32) | (unsigned)(prefix + agg));
                s_prefix = prefix;
            }
        }
    }
    __syncthreads();
    int excl = s_prefix + (warp ? wsum[warp - 1] : 0) + s - v;
    if (i < n) { g_off[i] = excl; g_cur[i] = excl; }
    if (i == 0) g_off[n] = total;
}

__global__ void k_scatter(const void* ei, int E, int ET) {
    int e = blockIdx.x * blockDim.x + threadIdx.x;
    if (e >= ET) return;
    int src, dst;
    if (e < E) load_edge(ei, E, e, src, dst);
    else       src = dst = e - E;
    float s  = g_ssrc[src] + g_sdst[dst];
    float lr = (s > 0.f) ? s : 0.01f * s;
    float w  = expf(lr);
    int pos = atomicAdd(&g_cur[dst], 1);
    g_sw[pos] = make_float2(__int_as_float(src), w);
}

// ---------------- gather: one warp per dst node ----------------------------
__global__ void k_gather(float* __restrict__ out, int N) {
    int gw   = (blockIdx.x * blockDim.x + threadIdx.x) >> 5;
    int lane = threadIdx.x & 31;
    if (gw >= N) return;
    int beg = g_off[gw];
    int end = g_off[gw + 1];
    float4 acc = make_float4(0.f, 0.f, 0.f, 0.f);
    float denom = 0.f;
    int e = beg;
    for (; e + 4 <= end; e += 4) {
        float2 sw0 = g_sw[e],     sw1 = g_sw[e + 1];
        float2 sw2 = g_sw[e + 2], sw3 = g_sw[e + 3];
        const float4 m0 = *(const float4*)&g_msg[(size_t)__float_as_int(sw0.x) * F + lane * 4];
        const float4 m1 = *(const float4*)&g_msg[(size_t)__float_as_int(sw1.x) * F + lane * 4];
        const float4 m2 = *(const float4*)&g_msg[(size_t)__float_as_int(sw2.x) * F + lane * 4];
        const float4 m3 = *(const float4*)&g_msg[(size_t)__float_as_int(sw3.x) * F + lane * 4];
        float w0 = sw0.y, w1 = sw1.y, w2 = sw2.y, w3 = sw3.y;
        denom += (w0 + w1) + (w2 + w3);
        acc.x += w0 * m0.x + w1 * m1.x + w2 * m2.x + w3 * m3.x;
        acc.y += w0 * m0.y + w1 * m1.y + w2 * m2.y + w3 * m3.y;
        acc.z += w0 * m0.z + w1 * m1.z + w2 * m2.z + w3 * m3.z;
        acc.w += w0 * m0.w + w1 * m1.w + w2 * m2.w + w3 * m3.w;
    }
    for (; e < end; ++e) {
        float2 sw0 = g_sw[e];
        float w0 = sw0.y;
        const float4 m0 = *(const float4*)&g_msg[(size_t)__float_as_int(sw0.x) * F + lane * 4];
        denom += w0;
        acc.x += w0 * m0.x; acc.y += w0 * m0.y;
        acc.z += w0 * m0.z; acc.w += w0 * m0.w;
    }
    float inv = 1.f / fmaxf(denom, 1e-12f);
    float4 o = make_float4(acc.x * inv, acc.y * inv, acc.z * inv, acc.w * inv);
    *reinterpret_cast<float4*>(&out[(size_t)gw * F + lane * 4]) = o;
}

// ---------------------------------------------------------------------------
extern "C" void kernel_launch(void* const* d_in, const int* in_sizes, int n_in,
                              void* d_out, int out_size) {
    const float* x  = (const float*)d_in[0];
    const void*  ei = d_in[1];
    const float* W  = (const float*)d_in[2];
    const float* a  = (const float*)d_in[3];
    float* out = (float*)d_out;

    int N  = in_sizes[0] / F;
    int E  = in_sizes[1] / 2;
    int ET = E + N;
    int NB = (N + 1023) / 1024;

    cudaFuncSetAttribute(k_gemm, cudaFuncAttributeMaxDynamicSharedMemorySize,
                         GEMM_SMEM_BYTES);

    k_init<<<(N + 255) / 256, 256>>>((const int*)ei, W, N);
    k_gemm<<<(N + 127) / 128, 256, GEMM_SMEM_BYTES>>>(x, a, ei, N, E, ET);
    k_scan<<<NB, 1024>>>(N, ET);
    k_scatter<<<(ET + 255) / 256, 256>>>(ei, E, ET);
    k_gather<<<(N + 7) / 8, 256>>>(out, N);
}

// round 16
// speedup vs baseline: 1.0007x; 1.0007x over previous
#include <cuda_runtime.h>
#include <cuda_bf16.h>
#include <math.h>

// ---------------------------------------------------------------------------
// GAT layer on GB300.
//  msg = x @ W^T  (bf16x2 tensor-core GEMM m16n8k16, W pre-converted to
//                  packed mma fragments held in L1 via LDG)
//  s_src/s_dst fused into GEMM epilogue; edge histogram fused into GEMM tail
//  CSR-by-dst build (fused histogram -> warp-lookback scan -> counting sort)
//  warp-per-node gather (no float atomics)
// ---------------------------------------------------------------------------

#define MAXN   50048
#define MAXE   600064
#define MAXET  (MAXN + MAXE)
#define F      128
#define PAD    132
#define NFRAG  (8 * 16 * 32)   // (ka, j, lane) bf16 B fragments
#define FULLM  0xffffffffu

__device__ float  g_msg[(size_t)MAXN * F];
__device__ float  g_ssrc[MAXN];
__device__ float  g_sdst[MAXN];
__device__ int    g_deg[MAXN];
__device__ int    g_off[MAXN + 1];
__device__ int    g_cur[MAXN];
__device__ float2 g_sw[MAXET];            // packed (src_bits, w)
__device__ unsigned long long g_lbk[64];  // lookback: (state<<32)|value
__device__ int    g_is64;
__device__ uint4  g_bfrag[NFRAG];         // (bh0,bh1,bl0,bl1) per (ka,j,lane)

// ---------------- init: zero hist/lookback + dtype detect + W frag cvt -----
__global__ void k_init(const int* __restrict__ ei32, const float* __restrict__ W,
                       int N) {
    __shared__ int sh[256];
    int i = blockIdx.x * blockDim.x + threadIdx.x;
    if (i < N) g_deg[i] = 0;
    if (i < 64) g_lbk[i] = 0ull;
    // W -> bf16x2 mma fragments (first 4096 threads)
    if (i < NFRAG) {
        int lane = i & 31, j = (i >> 5) & 15, ka = i >> 9;   // ka 0..7
        int g = lane >> 2, tg = lane & 3;
        int row = 8 * j + g, k0 = 16 * ka;
        float f0 = W[row * F + k0 + 2 * tg];
        float f1 = W[row * F + k0 + 2 * tg + 1];
        float f2 = W[row * F + k0 + 2 * tg + 8];
        float f3 = W[row * F + k0 + 2 * tg + 9];
        __nv_bfloat162 h0 = __floats2bfloat162_rn(f0, f1);
        __nv_bfloat162 h1 = __floats2bfloat162_rn(f2, f3);
        __nv_bfloat162 l0 = __floats2bfloat162_rn(f0 - __bfloat162float(h0.x),
                                                  f1 - __bfloat162float(h0.y));
        __nv_bfloat162 l1 = __floats2bfloat162_rn(f2 - __bfloat162float(h1.x),
                                                  f3 - __bfloat162float(h1.y));
        g_bfrag[i] = make_uint4(*(unsigned*)&h0, *(unsigned*)&h1,
                                *(unsigned*)&l0, *(unsigned*)&l1);
    }
    if (blockIdx.x == 0) {
        int any = 0;
        for (int t = threadIdx.x; t < 512; t += 256) any |= ei32[2 * t + 1];
        sh[threadIdx.x] = any;
        __syncthreads();
        for (int s = 128; s > 0; s >>= 1) {
            if (threadIdx.x < s) sh[threadIdx.x] |= sh[threadIdx.x + s];
            __syncthreads();
        }
        if (threadIdx.x == 0) g_is64 = (sh[0] == 0) ? 1 : 0;
    }
}

// ---------------- bf16 mma -------------------------------------------------
__device__ __forceinline__ void mma16(float* c,
                                      unsigned a0, unsigned a1, unsigned a2, unsigned a3,
                                      unsigned b0, unsigned b1) {
    asm volatile(
        "mma.sync.aligned.m16n8k16.row.col.f32.bf16.bf16.f32 "
        "{%0,%1,%2,%3}, {%4,%5,%6,%7}, {%8,%9}, {%0,%1,%2,%3};\n"
        : "+f"(c[0]), "+f"(c[1]), "+f"(c[2]), "+f"(c[3])
        : "r"(a0), "r"(a1), "r"(a2), "r"(a3), "r"(b0), "r"(b1));
}

// ---------------- GEMM: msg = x @ W^T (bf16x2) + scores + fused histogram --
// Block: 128 nodes x 128 feats, 256 threads (8 warps), each warp 16 rows.
#define GEMM_SMEM_BYTES ((F * PAD + 2 * F) * (int)sizeof(float))

__global__ void __launch_bounds__(256) k_gemm(const float* __restrict__ x,
                                              const float* __restrict__ a,
                                              const void* __restrict__ ei,
                                              int N, int E, int ET) {
    extern __shared__ float smem[];
    float* As = smem;               // F x PAD
    float* av = smem + F * PAD;     // 2F floats

    const int tid  = threadIdx.x;
    const int warp = tid >> 5;
    const int lane = tid & 31;
    const int g    = lane >> 2;      // 0..7
    const int tg   = lane & 3;       // 0..3
    const int m0   = blockIdx.x * 128;

    if (tid < 256) av[tid] = a[tid];
    for (int idx = tid; idx < F * 32; idx += 256) {
        int r = idx >> 5, c4 = idx & 31;
        int row = m0 + r;
        float4 v = (row < N) ? ((const float4*)x)[(size_t)row * 32 + c4]
                             : make_float4(0.f, 0.f, 0.f, 0.f);
        *(float4*)&As[r * PAD + c4 * 4] = v;
    }
    __syncthreads();

    float acc[16][4];
    #pragma unroll
    for (int j = 0; j < 16; ++j)
        acc[j][0] = acc[j][1] = acc[j][2] = acc[j][3] = 0.f;

    const int mw  = warp * 16;
    const int r0i = (mw + g) * PAD;
    const int r1i = (mw + g + 8) * PAD;
    const uint4* __restrict__ bf = g_bfrag + lane;

    #pragma unroll
    for (int ka = 0; ka < 8; ++ka) {
        const int k0 = ka * 16 + 2 * tg;
        float2 p00 = *(const float2*)&As[r0i + k0];
        float2 p01 = *(const float2*)&As[r0i + k0 + 8];
        float2 p10 = *(const float2*)&As[r1i + k0];
        float2 p11 = *(const float2*)&As[r1i + k0 + 8];

        __nv_bfloat162 h0 = __floats2bfloat162_rn(p00.x, p00.y);
        __nv_bfloat162 h1 = __floats2bfloat162_rn(p10.x, p10.y);
        __nv_bfloat162 h2 = __floats2bfloat162_rn(p01.x, p01.y);
        __nv_bfloat162 h3 = __floats2bfloat162_rn(p11.x, p11.y);
        __nv_bfloat162 l0 = __floats2bfloat162_rn(p00.x - __bfloat162float(h0.x),
                                                  p00.y - __bfloat162float(h0.y));
        __nv_bfloat162 l1 = __floats2bfloat162_rn(p10.x - __bfloat162float(h1.x),
                                                  p10.y - __bfloat162float(h1.y));
        __nv_bfloat162 l2 = __floats2bfloat162_rn(p01.x - __bfloat162float(h2.x),
                                                  p01.y - __bfloat162float(h2.y));
        __nv_bfloat162 l3 = __floats2bfloat162_rn(p11.x - __bfloat162float(h3.x),
                                                  p11.y - __bfloat162float(h3.y));
        unsigned ah0 = *(unsigned*)&h0, ah1 = *(unsigned*)&h1;
        unsigned ah2 = *(unsigned*)&h2, ah3 = *(unsigned*)&h3;
        unsigned al0 = *(unsigned*)&l0, al1 = *(unsigned*)&l1;
        unsigned al2 = *(unsigned*)&l2, al3 = *(unsigned*)&l3;

        #pragma unroll
        for (int j = 0; j < 16; ++j) {
            uint4 b = __ldg(bf + (ka * 16 + j) * 32);
            mma16(acc[j], ah0, ah1, ah2, ah3, b.x, b.y);  // hi*hi
            mma16(acc[j], ah0, ah1, ah2, ah3, b.z, b.w);  // hi*lo
            mma16(acc[j], al0, al1, al2, al3, b.x, b.y);  // lo*hi
        }
    }

    // ---- fused attention scores: s = msg @ a -------------------------------
    float p0 = 0.f, q0 = 0.f, p1 = 0.f, q1 = 0.f;  // rows g, g+8
    #pragma unroll
    for (int j = 0; j < 16; ++j) {
        int c = 8 * j + 2 * tg;
        p0 += acc[j][0] * av[c]       + acc[j][1] * av[c + 1];
        q0 += acc[j][0] * av[F + c]   + acc[j][1] * av[F + c + 1];
        p1 += acc[j][2] * av[c]       + acc[j][3] * av[c + 1];
        q1 += acc[j][2] * av[F + c]   + acc[j][3] * av[F + c + 1];
    }
    #pragma unroll
    for (int off = 1; off < 4; off <<= 1) {
        p0 += __shfl_xor_sync(FULLM, p0, off);
        q0 += __shfl_xor_sync(FULLM, q0, off);
        p1 += __shfl_xor_sync(FULLM, p1, off);
        q1 += __shfl_xor_sync(FULLM, q1, off);
    }
    if (tg == 0) {
        int r0 = m0 + mw + g, r1 = r0 + 8;
        if (r0 < N) { g_ssrc[r0] = p0; g_sdst[r0] = q0; }
        if (r1 < N) { g_ssrc[r1] = p1; g_sdst[r1] = q1; }
    }

    // ---- stage accumulators to (warp-private) SMEM, store coalesced --------
    __syncwarp();
    #pragma unroll
    for (int j = 0; j < 16; ++j) {
        int c = 8 * j + 2 * tg;
        *(float2*)&As[r0i + c] = make_float2(acc[j][0], acc[j][1]);
        *(float2*)&As[r1i + c] = make_float2(acc[j][2], acc[j][3]);
    }
    __syncwarp();
    for (int idx = lane; idx < 512; idx += 32) {
        int r = idx >> 5, c4 = idx & 31;
        int row = m0 + mw + r;
        if (row < N)
            *(float4*)&g_msg[(size_t)row * F + c4 * 4] =
                *(float4*)&As[(mw + r) * PAD + c4 * 4];
    }

    // ---- fused degree histogram chunk (independent of GEMM results) --------
    {
        int per = (ET + gridDim.x - 1) / gridDim.x;
        int e0 = blockIdx.x * per;
        int e1 = min(e0 + per, ET);
        if (g_is64) {
            const long long* __restrict__ pd = (const long long*)ei + E;
            for (int e = e0 + tid; e < e1; e += 256) {
                int dst = (e < E) ? (int)pd[e] : e - E;
                atomicAdd(&g_deg[dst], 1);
            }
        } else {
            const int* __restrict__ pd = (const int*)ei + E;
            for (int e = e0 + tid; e < e1; e += 256) {
                int dst = (e < E) ? pd[e] : e - E;
                atomicAdd(&g_deg[dst], 1);
            }
        }
    }
}

// Single-kernel decoupled-lookback exclusive scan (warp-parallel lookback).
__global__ void k_scan(int n, int total) {
    __shared__ int wsum[32];
    __shared__ int s_prefix;
    const int tid = threadIdx.x, lane = tid & 31, warp = tid >> 5;
    const int b = blockIdx.x;
    const int i = b * 1024 + tid;
    int v = (i < n) ? g_deg[i] : 0;
    int s = v;
    #pragma unroll
    for (int off = 1; off < 32; off <<= 1) {
        int t = __shfl_up_sync(FULLM, s, off);
        if (lane >= off) s += t;
    }
    if (lane == 31) wsum[warp] = s;
    __syncthreads();
    if (warp == 0) {
        int ws = wsum[lane];
        #pragma unroll
        for (int off = 1; off < 32; off <<= 1) {
            int t = __shfl_up_sync(FULLM, ws, off);
            if (lane >= off) ws += t;
        }
        wsum[lane] = ws;
    }
    __syncthreads();
    int agg = wsum[31];

    if (warp == 0) {
        if (b == 0) {
            if (lane == 0) {
                atomicExch(&g_lbk[0], (2ull << 32) | (unsigned)agg);
                s_prefix = 0;
            }
        } else {
            if (lane == 0)
                atomicExch(&g_lbk[b], (1ull << 32) | (unsigned)agg);
            __syncwarp();
            // warp-parallel lookback: lane L inspects predecessor b-1-L
            int prefix = 0;
            int p = b - 1 - lane;
            while (true) {
                unsigned long long val = (p >= 0)
                    ? *(volatile unsigned long long*)&g_lbk[p]
                    : (2ull << 32);
                unsigned st = (unsigned)(val >> 32);
                if (!__all_sync(FULLM, st != 0)) continue;   // retry window
                unsigned m2 = __ballot_sync(FULLM, st == 2);
                if (m2) {
                    int l2 = __ffs(m2) - 1;  // closest inclusive-prefix block
                    int contrib = (lane <= l2) ? (int)(unsigned)val : 0;
                    prefix += __reduce_add_sync(FULLM, contrib);
                    break;
                } else {
                    prefix += __reduce_add_sync(FULLM, (int)(unsigned)val);
                    p -= 32;
                }
            }
            if (lane == 0) {
                atomicExch(&g_lbk[b], (2ull << 32) | (unsigned)(prefix + agg));
                s_prefix = prefix;
            }
        }
    }
    __syncthreads();
    int excl = s_prefix + (warp ? wsum[warp - 1] : 0) + s - v;
    if (i < n) { g_off[i] = excl; g_cur[i] = excl; }
    if (i == 0) g_off[n] = total;
}

// ---------------- scatter: 4 edges per thread for MLP ----------------------
__global__ void k_scatter(const void* ei, int E, int ET) {
    const int base = blockIdx.x * 1024;          // 4 edges x 256 threads
    const int tid  = threadIdx.x;
    const int is64 = g_is64;

    int src[4], dst[4];
    float w[4];
    int cnt = 0;
    #pragma unroll
    for (int u = 0; u < 4; ++u) {
        int e = base + u * 256 + tid;
        if (e < ET) {
            int s, d;
            if (e < E) {
                if (is64) {
                    s = (int)((const long long*)ei)[e];
                    d = (int)((const long long*)ei)[E + e];
                } else {
                    s = ((const int*)ei)[e];
                    d = ((const int*)ei)[E + e];
                }
            } else {
                s = d = e - E;
            }
            src[u] = s; dst[u] = d; cnt = u + 1;
        }
    }
    float ss[4], sd[4];
    #pragma unroll
    for (int u = 0; u < 4; ++u)
        if (u < cnt) { ss[u] = g_ssrc[src[u]]; sd[u] = g_sdst[dst[u]]; }
    #pragma unroll
    for (int u = 0; u < 4; ++u)
        if (u < cnt) {
            float s  = ss[u] + sd[u];
            float lr = (s > 0.f) ? s : 0.01f * s;
            w[u] = expf(lr);
        }
    int pos[4];
    #pragma unroll
    for (int u = 0; u < 4; ++u)
        if (u < cnt) pos[u] = atomicAdd(&g_cur[dst[u]], 1);
    #pragma unroll
    for (int u = 0; u < 4; ++u)
        if (u < cnt) g_sw[pos[u]] = make_float2(__int_as_float(src[u]), w[u]);
}

// ---------------- gather: one warp per dst node ----------------------------
__global__ void k_gather(float* __restrict__ out, int N) {
    int gw   = (blockIdx.x * blockDim.x + threadIdx.x) >> 5;
    int lane = threadIdx.x & 31;
    if (gw >= N) return;
    int beg = g_off[gw];
    int end = g_off[gw + 1];
    float4 acc = make_float4(0.f, 0.f, 0.f, 0.f);
    float denom = 0.f;
    int e = beg;
    for (; e + 4 <= end; e += 4) {
        float2 sw0 = g_sw[e],     sw1 = g_sw[e + 1];
        float2 sw2 = g_sw[e + 2], sw3 = g_sw[e + 3];
        const float4 m0 = *(const float4*)&g_msg[(size_t)__float_as_int(sw0.x) * F + lane * 4];
        const float4 m1 = *(const float4*)&g_msg[(size_t)__float_as_int(sw1.x) * F + lane * 4];
        const float4 m2 = *(const float4*)&g_msg[(size_t)__float_as_int(sw2.x) * F + lane * 4];
        const float4 m3 = *(const float4*)&g_msg[(size_t)__float_as_int(sw3.x) * F + lane * 4];
        float w0 = sw0.y, w1 = sw1.y, w2 = sw2.y, w3 = sw3.y;
        denom += (w0 + w1) + (w2 + w3);
        acc.x += w0 * m0.x + w1 * m1.x + w2 * m2.x + w3 * m3.x;
        acc.y += w0 * m0.y + w1 * m1.y + w2 * m2.y + w3 * m3.y;
        acc.z += w0 * m0.z + w1 * m1.z + w2 * m2.z + w3 * m3.z;
        acc.w += w0 * m0.w + w1 * m1.w + w2 * m2.w + w3 * m3.w;
    }
    for (; e < end; ++e) {
        float2 sw0 = g_sw[e];
        float w0 = sw0.y;
        const float4 m0 = *(const float4*)&g_msg[(size_t)__float_as_int(sw0.x) * F + lane * 4];
        denom += w0;
        acc.x += w0 * m0.x; acc.y += w0 * m0.y;
        acc.z += w0 * m0.z; acc.w += w0 * m0.w;
    }
    float inv = 1.f / fmaxf(denom, 1e-12f);
    float4 o = make_float4(acc.x * inv, acc.y * inv, acc.z * inv, acc.w * inv);
    *reinterpret_cast<float4*>(&out[(size_t)gw * F + lane * 4]) = o;
}

// ---------------------------------------------------------------------------
extern "C" void kernel_launch(void* const* d_in, const int* in_sizes, int n_in,
                              void* d_out, int out_size) {
    const float* x  = (const float*)d_in[0];
    const void*  ei = d_in[1];
    const float* W  = (const float*)d_in[2];
    const float* a  = (const float*)d_in[3];
    float* out = (float*)d_out;

    int N  = in_sizes[0] / F;
    int E  = in_sizes[1] / 2;
    int ET = E + N;
    int NB = (N + 1023) / 1024;

    cudaFuncSetAttribute(k_gemm, cudaFuncAttributeMaxDynamicSharedMemorySize,
                         GEMM_SMEM_BYTES);

    k_init<<<(N + 255) / 256, 256>>>((const int*)ei, W, N);
    k_gemm<<<(N + 127) / 128, 256, GEMM_SMEM_BYTES>>>(x, a, ei, N, E, ET);
    k_scan<<<NB, 1024>>>(N, ET);
    k_scatter<<<(ET + 1023) / 1024, 256>>>(ei, E, ET);
    k_gather<<<(N + 7) / 8, 256>>>(out, N);
}